// round 6
// baseline (speedup 1.0000x reference)
#include <cuda_runtime.h>
#include <cfloat>
#include <cmath>

// Problem constants
#define TOKENS 16384
#define HID    4096
#define NEXP   64
#define TOPK   8

// Tiling
#define MT     128      // tokens per block
#define KC     32       // K chunk staged in SMEM (also the accumulation-chunk size)
#define NTHR   256
#define XS_STRIDE 132   // 128 rows + pad (multiple of 4 floats for vector ld/st)
#define WS_STRIDE 68    // 64 experts + pad

typedef unsigned long long ull;

// ---- packed f32x2 helpers (sm_100+ PTX) ----
__device__ __forceinline__ ull dup2(float v) {
    ull r;
    asm("mov.b64 %0, {%1, %1};" : "=l"(r) : "f"(v));
    return r;
}
__device__ __forceinline__ void fma2(ull& d, ull a, ull b) {
    asm("fma.rn.f32x2 %0, %1, %2, %0;" : "+l"(d) : "l"(a), "l"(b));
}
__device__ __forceinline__ ull add2(ull a, ull b) {
    ull r;
    asm("add.rn.f32x2 %0, %1, %2;" : "=l"(r) : "l"(a), "l"(b));
    return r;
}
// r = a*b + c  (3-operand form, for computing hi - t as fma(t, -1, hi))
__device__ __forceinline__ ull fma2v(ull a, ull b, ull c) {
    ull r;
    asm("fma.rn.f32x2 %0, %1, %2, %3;" : "=l"(r) : "l"(a), "l"(b), "l"(c));
    return r;
}
__device__ __forceinline__ void unpack2(ull v, float& lo, float& hi) {
    asm("mov.b64 {%0, %1}, %2;" : "=f"(lo), "=f"(hi) : "l"(v));
}

__global__ __launch_bounds__(NTHR)
void gating_kernel(const float* __restrict__ x,
                   const float* __restrict__ gw,
                   const float* __restrict__ gb,
                   float* __restrict__ out)
{
    // One buffer, two lives:
    //   GEMM phase:    xs_t[KC][XS_STRIDE] (4224 f) + ws_t[KC][WS_STRIDE] (2176 f)
    //   Epilogue:      logits[MT][NEXP] = 8192 floats
    __shared__ __align__(16) float smem[MT * NEXP];
    float* xs = smem;                         // k-major: xs[k*XS_STRIDE + row]
    float* ws = smem + KC * XS_STRIDE;        // k-major: ws[k*WS_STRIDE + expert]
    float* lg = smem;                         // logits[token*NEXP + expert]

    const int tid = threadIdx.x;
    const int ty  = tid >> 4;                 // 0..15  -> rows ty*8 .. ty*8+7
    const int tx  = tid & 15;                 // 0..15  -> cols tx*4 .. tx*4+3
    const int m0  = blockIdx.x * MT;

    // ---- global-load lane mapping (coalesced float4) ----
    float4 xr[4], wr[2];

    auto load_x = [&](int kbase) {
#pragma unroll
        for (int j = 0; j < 4; j++) {
            int i = tid + NTHR * j;
            int row = i >> 3;
            int k4  = (i & 7) * 4;
            xr[j] = *(const float4*)(x + (size_t)(m0 + row) * HID + kbase + k4);
        }
    };
    auto load_w = [&](int kbase) {
#pragma unroll
        for (int j = 0; j < 2; j++) {
            int i = tid + NTHR * j;
            int e  = i >> 3;
            int k4 = (i & 7) * 4;
            wr[j] = *(const float4*)(gw + (size_t)e * HID + kbase + k4);
        }
    };

    // Double-float outer accumulators (hi, lo) + per-chunk fp32 accumulator.
    // 8 rows x 4 cols per thread, packed in f32x2 pairs -> [4][4].
    ull acc_hi[4][4], acc_lo[4][4];
#pragma unroll
    for (int i = 0; i < 4; i++)
#pragma unroll
        for (int j = 0; j < 4; j++) { acc_hi[i][j] = 0ULL; acc_lo[i][j] = 0ULL; }

    const ull NEG1 = dup2(-1.0f);

    // preload chunk 0
    load_x(0);
    load_w(0);

    for (int k0 = 0; k0 < HID; k0 += KC) {
        __syncthreads();   // previous chunk's compute done before overwrite

        // stage current chunk to SMEM, transposed to k-major
#pragma unroll
        for (int j = 0; j < 4; j++) {
            int i = tid + NTHR * j;
            int row = i >> 3;
            int kb  = (i & 7) * 4;
            float* p = xs + kb * XS_STRIDE + row;
            p[0 * XS_STRIDE] = xr[j].x;
            p[1 * XS_STRIDE] = xr[j].y;
            p[2 * XS_STRIDE] = xr[j].z;
            p[3 * XS_STRIDE] = xr[j].w;
        }
#pragma unroll
        for (int j = 0; j < 2; j++) {
            int i = tid + NTHR * j;
            int e  = i >> 3;
            int kb = (i & 7) * 4;
            float* p = ws + kb * WS_STRIDE + e;
            p[0 * WS_STRIDE] = wr[j].x;
            p[1 * WS_STRIDE] = wr[j].y;
            p[2 * WS_STRIDE] = wr[j].z;
            p[3 * WS_STRIDE] = wr[j].w;
        }
        __syncthreads();

        // prefetch next chunk into registers (overlaps with compute below)
        int kn = k0 + KC;
        if (kn < HID) { load_x(kn); load_w(kn); }

        // fresh chunk accumulator (32 terms -> chunk error RMS ~2e-8 abs)
        ull cacc[4][4];
#pragma unroll
        for (int i = 0; i < 4; i++)
#pragma unroll
            for (int j = 0; j < 4; j++) cacc[i][j] = 0ULL;

        // compute: 32 k-steps, 8x4 microtile, 16 FFMA2 per step
#pragma unroll
        for (int kk = 0; kk < KC; kk++) {
            const float* ap = xs + kk * XS_STRIDE + ty * 8;
            double2 a01 = *(const double2*)(ap);        // rows (0,1),(2,3)
            double2 a23 = *(const double2*)(ap + 4);    // rows (4,5),(6,7)
            float4  b   = *(const float4*)(ws + kk * WS_STRIDE + tx * 4);

            ull a[4] = { __double_as_longlong(a01.x), __double_as_longlong(a01.y),
                         __double_as_longlong(a23.x), __double_as_longlong(a23.y) };
            ull bd[4] = { dup2(b.x), dup2(b.y), dup2(b.z), dup2(b.w) };

#pragma unroll
            for (int rp = 0; rp < 4; rp++)
#pragma unroll
                for (int c = 0; c < 4; c++) fma2(cacc[rp][c], a[rp], bd[c]);
        }

        // Fast2Sum flush: (hi, lo) += chunk   [4 packed ops per accumulator]
        //   t  = hi + v
        //   e  = (hi - t) + v       (hi - t via fma(t, -1, hi))
        //   lo += e ; hi = t
#pragma unroll
        for (int rp = 0; rp < 4; rp++)
#pragma unroll
            for (int c = 0; c < 4; c++) {
                ull v = cacc[rp][c];
                ull t = add2(acc_hi[rp][c], v);
                ull e = add2(fma2v(t, NEG1, acc_hi[rp][c]), v);
                acc_lo[rp][c] = add2(acc_lo[rp][c], e);
                acc_hi[rp][c] = t;
            }
    }

    // ---- epilogue: logits = hi + lo + bias -> SMEM (reuse buffer) ----
    __syncthreads();

    float4 bias4 = *(const float4*)(gb + tx * 4);
    const float bias[4] = { bias4.x, bias4.y, bias4.z, bias4.w };

#pragma unroll
    for (int rp = 0; rp < 4; rp++) {
#pragma unroll
        for (int c = 0; c < 4; c++) {
            ull s = add2(acc_hi[rp][c], acc_lo[rp][c]);
            float lo, hi;
            unpack2(s, lo, hi);
            int col = tx * 4 + c;
            int r   = ty * 8 + rp * 2;
            lg[(r    ) * NEXP + col] = lo + bias[c];
            lg[(r + 1) * NEXP + col] = hi + bias[c];
        }
    }
    __syncthreads();

    // ---- top-8 + softmax: one warp per token ----
    const unsigned FULL = 0xffffffffu;
    const int warp = tid >> 5;
    const int lane = tid & 31;
    float* outw = out;                         // (TOKENS, 8) weights
    float* outi = out + (size_t)TOKENS * TOPK; // (TOKENS, 8) indices (as f32)

    for (int t = warp; t < MT; t += 8) {
        float v0 = lg[t * NEXP + lane];
        float v1 = lg[t * NEXP + lane + 32];
        int   i0 = lane;
        int   i1 = lane + 32;

        float m = 0.f, ssum = 0.f, myv = 0.f;
        int myi = 0;

#pragma unroll
        for (int s = 0; s < TOPK; s++) {
            // local best of the 2 values this lane holds (tie -> smaller idx)
            float v; int idx;
            if (v0 > v1 || (v0 == v1 && i0 < i1)) { v = v0; idx = i0; }
            else                                  { v = v1; idx = i1; }
            // warp argmax, tie -> smaller idx (matches jax.lax.top_k stability)
#pragma unroll
            for (int off = 16; off > 0; off >>= 1) {
                float ov = __shfl_down_sync(FULL, v,   off);
                int   oi = __shfl_down_sync(FULL, idx, off);
                if (ov > v || (ov == v && oi < idx)) { v = ov; idx = oi; }
            }
            v   = __shfl_sync(FULL, v,   0);
            idx = __shfl_sync(FULL, idx, 0);

            if (s == 0) m = v;               // max (sorted descending)
            ssum += expf(v - m);
            if (lane == s) { myv = v; myi = idx; }

            if (idx == i0) v0 = -FLT_MAX;
            if (idx == i1) v1 = -FLT_MAX;
        }

        if (lane < TOPK) {
            int g = (m0 + t) * TOPK + lane;
            outw[g] = expf(myv - m) / ssum;
            outi[g] = (float)myi;
        }
    }
}

extern "C" void kernel_launch(void* const* d_in, const int* in_sizes, int n_in,
                              void* d_out, int out_size)
{
    const float* x  = (const float*)d_in[0];   // (16384, 4096) f32
    const float* gw = (const float*)d_in[1];   // (64, 4096)    f32
    const float* gb = (const float*)d_in[2];   // (64,)         f32
    float* out = (float*)d_out;                // [weights | indices] as f32

    gating_kernel<<<TOKENS / MT, NTHR>>>(x, gw, gb, out);
}

// round 10
// speedup vs baseline: 1.6028x; 1.6028x over previous
#include <cuda_runtime.h>
#include <cfloat>
#include <cmath>
#include <cstdint>

// ---- problem ----
#define TOKENS 16384
#define HID    4096
#define NEXP   64
#define TOPK   8

// ---- tiling ----
#define MT     128            // tokens per block
#define KC     32             // K per chunk
#define NCH    (HID / KC)     // 128 chunks
#define NTHR   256
#define SPLITB 4096           // one bf16 split of B chunk: 64n x 32k x 2B
#define BUFB   (3 * SPLITB)   // 12288
// smem: [0, 32768) = B double-buffer (24576) reused as logits (32768); bias at 32768
#define SMEM_BYTES (32768 + 256)

typedef unsigned long long ull;
typedef uint32_t u32;

// ---- PTX helpers (all plain-sm_103-safe) ----
__device__ __forceinline__ u32 smem_u32(const void* p) {
    u32 a;
    asm("{ .reg .u64 t; cvta.to.shared.u64 t, %1; cvt.u32.u64 %0, t; }"
        : "=r"(a) : "l"(p));
    return a;
}
__device__ __forceinline__ void ldsm4(u32& r0, u32& r1, u32& r2, u32& r3, u32 a) {
    asm volatile("ldmatrix.sync.aligned.m8n8.x4.shared.b16 {%0,%1,%2,%3}, [%4];"
                 : "=r"(r0), "=r"(r1), "=r"(r2), "=r"(r3) : "r"(a));
}
__device__ __forceinline__ void mma16816(float* c, const u32* a, u32 b0, u32 b1) {
    asm volatile(
        "mma.sync.aligned.m16n8k16.row.col.f32.bf16.bf16.f32 "
        "{%0,%1,%2,%3}, {%4,%5,%6,%7}, {%8,%9}, {%0,%1,%2,%3};"
        : "+f"(c[0]), "+f"(c[1]), "+f"(c[2]), "+f"(c[3])
        : "r"(a[0]), "r"(a[1]), "r"(a[2]), "r"(a[3]), "r"(b0), "r"(b1));
}

// ---- exact fp32 -> 3x bf16 split (packed f32x2, fast-math-immune) ----
__device__ __forceinline__ u32 cvtbf2(float lo, float hi) {
    u32 r;
    asm("cvt.rn.satfinite.bf16x2.f32 %0, %1, %2;" : "=r"(r) : "f"(hi), "f"(lo));
    return r;   // low half = lo (lower-k element), matches mma packing
}
__device__ __forceinline__ ull expandbf(u32 p) {   // bf16x2 -> f32x2 (exact)
    u32 lo = p << 16, hi = p & 0xFFFF0000u;
    ull r;
    asm("mov.b64 %0, {%1, %2};" : "=l"(r) : "r"(lo), "r"(hi));
    return r;
}
__device__ __forceinline__ ull packf2(float lo, float hi) {
    ull r;
    asm("mov.b64 %0, {%1, %2};" : "=l"(r) : "f"(lo), "f"(hi));
    return r;
}
__device__ __forceinline__ void unpackf2(ull v, float& lo, float& hi) {
    asm("mov.b64 {%0, %1}, %2;" : "=f"(lo), "=f"(hi) : "l"(v));
}
__device__ __forceinline__ ull fma2v(ull a, ull b, ull c) {
    ull r;
    asm("fma.rn.f32x2 %0, %1, %2, %3;" : "=l"(r) : "l"(a), "l"(b), "l"(c));
    return r;
}
__device__ __forceinline__ float fadd_rn(float a, float b) {
    float r; asm("add.rn.f32 %0, %1, %2;" : "=f"(r) : "f"(a), "f"(b)); return r;
}
__device__ __forceinline__ float fsub_rn(float a, float b) {
    float r; asm("sub.rn.f32 %0, %1, %2;" : "=f"(r) : "f"(a), "f"(b)); return r;
}
__device__ __forceinline__ void dfadd(float& h, float& l, float v) {
    float t = fadd_rn(h, v);
    float e = fadd_rn(fsub_rn(h, t), v);   // exact when |h| >= |v|
    l = fadd_rn(l, e);
    h = t;
}
__device__ __forceinline__ void split2f(float vlo, float vhi, ull neg1,
                                        u32& q0, u32& q1, u32& q2) {
    ull v = packf2(vlo, vhi);
    q0 = cvtbf2(vlo, vhi);
    ull r1 = fma2v(expandbf(q0), neg1, v);     // v - (f32)q0, exact
    float rl, rh; unpackf2(r1, rl, rh);
    q1 = cvtbf2(rl, rh);
    ull r2 = fma2v(expandbf(q1), neg1, r1);    // second residual
    float sl, sh; unpackf2(r2, sl, sh);
    q2 = cvtbf2(sl, sh);
}

__global__ __launch_bounds__(NTHR, 1)
void gating_kernel(const float* __restrict__ x,
                   const float* __restrict__ gw,
                   const float* __restrict__ gb,
                   float* __restrict__ out)
{
    __shared__ __align__(16) char sm[SMEM_BYTES];
    float* lg  = (float*)sm;                 // logits, reuses B region
    float* gbs = (float*)(sm + 32768);       // bias
    const u32 sb = smem_u32(sm);

    const int tid  = threadIdx.x;
    const int wid  = tid >> 5;
    const int lane = tid & 31;
    const int m0   = blockIdx.x * MT;

    if (tid < NEXP) gbs[tid] = gb[tid];

    const ull NEG1 = packf2(-1.0f, -1.0f);

    // ---- per-thread A fragment source addresses (direct global -> register) ----
    // warp owns rows [16*wid, 16*wid+16); thread: rows lane/4 and lane/4+8
    const int ar = m0 + wid * 16 + (lane >> 2);
    const float* xp0 = x + (size_t)ar * HID + (lane & 3) * 2;
    const float* xp1 = xp0 + (size_t)8 * HID;

    // ---- B conversion mapping: thread -> (n = tid/4, k-tile kt = tid%4) ----
    const int bn  = tid >> 2;
    const int bkt = tid & 3;
    const float* wp = gw + (size_t)bn * HID + bkt * 8;
    // tile-contiguous layout: 8x8 tiles of bf16 (8 rows x 16B), tile = (n/8)*4 + kt,
    // per-tile row rotation rn^kt for bank-conflict-free ldmatrix + STS.128
    const int bst = (((bn >> 3) * 4 + bkt) * 8 + ((bn & 7) ^ bkt)) * 16;

    // ---- accumulators ----
    float ah[8][4], al[8][4], aM[8][4], aC[8][4];
#pragma unroll
    for (int i = 0; i < 8; i++)
#pragma unroll
        for (int j = 0; j < 4; j++) { ah[i][j] = 0.f; al[i][j] = 0.f; aM[i][j] = 0.f; aC[i][j] = 0.f; }

    // ---- prefetch chunk 0 ----
    float2 xc[2][2][2], xn[2][2][2];   // [row01][kstep][khalf]
    float4 wc[2], wn[2];
#pragma unroll
    for (int s = 0; s < 2; s++)
#pragma unroll
        for (int u = 0; u < 2; u++) {
            xc[0][s][u] = *(const float2*)(xp0 + s * 16 + u * 8);
            xc[1][s][u] = *(const float2*)(xp1 + s * 16 + u * 8);
        }
    wc[0] = *(const float4*)(wp);
    wc[1] = *(const float4*)(wp + 4);

#pragma unroll 1
    for (int c = 0; c < NCH; ++c) {
        const int buf = c & 1;

        // ---- convert + store B chunk (each thread: 8 floats -> 3x4 u32, 3 STS.128) ----
        {
            u32 s0[4], s1[4], s2[4];
            split2f(wc[0].x, wc[0].y, NEG1, s0[0], s1[0], s2[0]);
            split2f(wc[0].z, wc[0].w, NEG1, s0[1], s1[1], s2[1]);
            split2f(wc[1].x, wc[1].y, NEG1, s0[2], s1[2], s2[2]);
            split2f(wc[1].z, wc[1].w, NEG1, s0[3], s1[3], s2[3]);
            char* p = sm + buf * BUFB + bst;
            *(uint4*)(p)              = make_uint4(s0[0], s0[1], s0[2], s0[3]);
            *(uint4*)(p + SPLITB)     = make_uint4(s1[0], s1[1], s1[2], s1[3]);
            *(uint4*)(p + 2 * SPLITB) = make_uint4(s2[0], s2[1], s2[2], s2[3]);
        }
        __syncthreads();

        // ---- prefetch next chunk into registers (hidden under mma) ----
        const int cn = (c + 1 < NCH) ? (c + 1) * KC : 0;
#pragma unroll
        for (int s = 0; s < 2; s++)
#pragma unroll
            for (int u = 0; u < 2; u++) {
                xn[0][s][u] = *(const float2*)(xp0 + cn + s * 16 + u * 8);
                xn[1][s][u] = *(const float2*)(xp1 + cn + s * 16 + u * 8);
            }
        wn[0] = *(const float4*)(wp + cn);
        wn[1] = *(const float4*)(wp + cn + 4);

        // ---- mma phase ----
        const u32 bb = sb + buf * BUFB;
        const int g = lane >> 3, r = lane & 7;   // ldmatrix lane-group / row

#pragma unroll
        for (int s = 0; s < 2; s++) {
            // A fragments for this k16-step: split in-register
            u32 af0[4], af1[4], af2[4];
            split2f(xc[0][s][0].x, xc[0][s][0].y, NEG1, af0[0], af1[0], af2[0]);
            split2f(xc[1][s][0].x, xc[1][s][0].y, NEG1, af0[1], af1[1], af2[1]);
            split2f(xc[0][s][1].x, xc[0][s][1].y, NEG1, af0[2], af1[2], af2[2]);
            split2f(xc[1][s][1].x, xc[1][s][1].y, NEG1, af0[3], af1[3], af2[3]);

#pragma unroll
            for (int tp = 0; tp < 4; tp++) {
                // B fragments for n-tiles (2tp, 2tp+1), k-step s, all 3 splits
                const int tn = tp * 2 + (g >> 1);
                const int kt = s * 2 + (g & 1);
                const u32 ad = bb + (u32)(((tn * 4 + kt) * 8 + (r ^ kt)) * 16);
                u32 b0[4], b1[4], b2[4];
                ldsm4(b0[0], b0[1], b0[2], b0[3], ad);
                ldsm4(b1[0], b1[1], b1[2], b1[3], ad + SPLITB);
                ldsm4(b2[0], b2[1], b2[2], b2[3], ad + 2 * SPLITB);

#pragma unroll
                for (int t2 = 0; t2 < 2; t2++) {
                    float* M = aM[tp * 2 + t2];
                    float* C = aC[tp * 2 + t2];
                    const u32 p0 = b0[2 * t2], p1 = b0[2 * t2 + 1];
                    const u32 q0 = b1[2 * t2], q1 = b1[2 * t2 + 1];
                    const u32 r0 = b2[2 * t2], r1 = b2[2 * t2 + 1];
                    mma16816(M, af0, p0, p1);          // main a0*b0
                    mma16816(C, af0, q0, q1);          // a0*b1
                    mma16816(C, af1, p0, p1);          // a1*b0
                    mma16816(C, af0, r0, r1);          // a0*b2
                    mma16816(C, af1, q0, q1);          // a1*b1
                    mma16816(C, af2, p0, p1);          // a2*b0
                }
            }
        }

        // ---- Fast2Sum flush of main accumulator every 2 chunks (K=64) ----
        if (c & 1) {
#pragma unroll
            for (int i = 0; i < 8; i++)
#pragma unroll
                for (int j = 0; j < 4; j++) {
                    dfadd(ah[i][j], al[i][j], aM[i][j]);
                    aM[i][j] = 0.f;
                }
        }

        // rotate prefetch registers
#pragma unroll
        for (int a = 0; a < 2; a++)
#pragma unroll
            for (int s = 0; s < 2; s++)
#pragma unroll
                for (int u = 0; u < 2; u++) xc[a][s][u] = xn[a][s][u];
        wc[0] = wn[0]; wc[1] = wn[1];
    }

    __syncthreads();   // all mma reads of B region done before logits overwrite

    // ---- logits = ah + (al + corrections) + bias -> smem ----
    {
        const int row0 = wid * 16 + (lane >> 2);
#pragma unroll
        for (int t = 0; t < 8; t++)
#pragma unroll
            for (int k = 0; k < 4; k++) {
                int row = row0 + ((k >> 1) ? 8 : 0);
                int col = t * 8 + (lane & 3) * 2 + (k & 1);
                float v = fadd_rn(ah[t][k], fadd_rn(al[t][k], aC[t][k]));
                lg[row * NEXP + col] = fadd_rn(v, gbs[col]);
            }
    }
    __syncthreads();

    // ---- top-8 + softmax: one warp per token ----
    const unsigned FULL = 0xffffffffu;
    float* outw = out;
    float* outi = out + (size_t)TOKENS * TOPK;

    for (int t = wid; t < MT; t += 8) {
        float v0 = lg[t * NEXP + lane];
        float v1 = lg[t * NEXP + lane + 32];
        int   i0 = lane, i1 = lane + 32;

        float m = 0.f, ssum = 0.f, myv = 0.f;
        int myi = 0;

#pragma unroll
        for (int s = 0; s < TOPK; s++) {
            float v; int idx;
            if (v0 > v1 || (v0 == v1 && i0 < i1)) { v = v0; idx = i0; }
            else                                  { v = v1; idx = i1; }
#pragma unroll
            for (int off = 16; off > 0; off >>= 1) {
                float ov = __shfl_down_sync(FULL, v,   off);
                int   oi = __shfl_down_sync(FULL, idx, off);
                if (ov > v || (ov == v && oi < idx)) { v = ov; idx = oi; }
            }
            v   = __shfl_sync(FULL, v,   0);
            idx = __shfl_sync(FULL, idx, 0);

            if (s == 0) m = v;               // max (sorted descending)
            ssum += expf(v - m);
            if (lane == s) { myv = v; myi = idx; }

            if (idx == i0) v0 = -FLT_MAX;
            if (idx == i1) v1 = -FLT_MAX;
        }

        if (lane < TOPK) {
            int gidx = (m0 + t) * TOPK + lane;
            outw[gidx] = expf(myv - m) / ssum;
            outi[gidx] = (float)myi;
        }
    }
}

extern "C" void kernel_launch(void* const* d_in, const int* in_sizes, int n_in,
                              void* d_out, int out_size)
{
    const float* x  = (const float*)d_in[0];   // (16384, 4096) f32
    const float* gw = (const float*)d_in[1];   // (64, 4096)    f32
    const float* gb = (const float*)d_in[2];   // (64,)         f32
    float* out = (float*)d_out;                // [weights | indices] as f32

    gating_kernel<<<TOKENS / MT, NTHR>>>(x, gw, gb, out);
}

// round 12
// speedup vs baseline: 1.6871x; 1.0525x over previous
#include <cuda_runtime.h>
#include <cfloat>
#include <cmath>
#include <cstdint>

// ---- problem ----
#define TOKENS 16384
#define HID    4096
#define NEXP   64
#define TOPK   8

// ---- tiling ----
#define MT     128            // tokens per block
#define KC     32             // K per chunk
#define NCH    (HID / KC)     // 128 chunks
#define NTHR   256
#define SPLITB 4096           // one bf16 split of B chunk: 64n x 32k x 2B
#define BUFB   (3 * SPLITB)   // 12288
// smem: [0, 32768) = B double-buffer (24576) reused as logits (32768); bias at 32768
#define SMEM_BYTES (32768 + 256)

typedef unsigned long long ull;
typedef uint32_t u32;

// ---- PTX helpers (all plain-sm_103-safe) ----
__device__ __forceinline__ u32 smem_u32(const void* p) {
    u32 a;
    asm("{ .reg .u64 t; cvta.to.shared.u64 t, %1; cvt.u32.u64 %0, t; }"
        : "=r"(a) : "l"(p));
    return a;
}
__device__ __forceinline__ void ldsm4(u32& r0, u32& r1, u32& r2, u32& r3, u32 a) {
    asm volatile("ldmatrix.sync.aligned.m8n8.x4.shared.b16 {%0,%1,%2,%3}, [%4];"
                 : "=r"(r0), "=r"(r1), "=r"(r2), "=r"(r3) : "r"(a));
}
__device__ __forceinline__ void mma16816(float* c, const u32* a, u32 b0, u32 b1) {
    asm volatile(
        "mma.sync.aligned.m16n8k16.row.col.f32.bf16.bf16.f32 "
        "{%0,%1,%2,%3}, {%4,%5,%6,%7}, {%8,%9}, {%0,%1,%2,%3};"
        : "+f"(c[0]), "+f"(c[1]), "+f"(c[2]), "+f"(c[3])
        : "r"(a[0]), "r"(a[1]), "r"(a[2]), "r"(a[3]), "r"(b0), "r"(b1));
}

// ---- exact fp32 -> 3x bf16 split (packed f32x2, fast-math-immune) ----
__device__ __forceinline__ u32 cvtbf2(float lo, float hi) {
    u32 r;
    asm("cvt.rn.satfinite.bf16x2.f32 %0, %1, %2;" : "=r"(r) : "f"(hi), "f"(lo));
    return r;   // low half = lo (lower-k element), matches mma packing
}
__device__ __forceinline__ ull expandbf(u32 p) {   // bf16x2 -> f32x2 (exact)
    u32 lo = p << 16, hi = p & 0xFFFF0000u;
    ull r;
    asm("mov.b64 %0, {%1, %2};" : "=l"(r) : "r"(lo), "r"(hi));
    return r;
}
__device__ __forceinline__ ull packf2(float lo, float hi) {
    ull r;
    asm("mov.b64 %0, {%1, %2};" : "=l"(r) : "f"(lo), "f"(hi));
    return r;
}
__device__ __forceinline__ void unpackf2(ull v, float& lo, float& hi) {
    asm("mov.b64 {%0, %1}, %2;" : "=f"(lo), "=f"(hi) : "l"(v));
}
__device__ __forceinline__ ull fma2v(ull a, ull b, ull c) {
    ull r;
    asm("fma.rn.f32x2 %0, %1, %2, %3;" : "=l"(r) : "l"(a), "l"(b), "l"(c));
    return r;
}
__device__ __forceinline__ float fadd_rn(float a, float b) {
    float r; asm("add.rn.f32 %0, %1, %2;" : "=f"(r) : "f"(a), "f"(b)); return r;
}
__device__ __forceinline__ float fsub_rn(float a, float b) {
    float r; asm("sub.rn.f32 %0, %1, %2;" : "=f"(r) : "f"(a), "f"(b)); return r;
}
__device__ __forceinline__ void dfadd(float& h, float& l, float v) {
    float t = fadd_rn(h, v);
    float e = fadd_rn(fsub_rn(h, t), v);   // exact when |h| >= |v|
    l = fadd_rn(l, e);
    h = t;
}
__device__ __forceinline__ void split2f(float vlo, float vhi, ull neg1,
                                        u32& q0, u32& q1, u32& q2) {
    ull v = packf2(vlo, vhi);
    q0 = cvtbf2(vlo, vhi);
    ull r1 = fma2v(expandbf(q0), neg1, v);     // v - (f32)q0, exact
    float rl, rh; unpackf2(r1, rl, rh);
    q1 = cvtbf2(rl, rh);
    ull r2 = fma2v(expandbf(q1), neg1, r1);    // second residual
    float sl, sh; unpackf2(r2, sl, sh);
    q2 = cvtbf2(sl, sh);
}

__global__ __launch_bounds__(NTHR, 1)
void gating_kernel(const float* __restrict__ x,
                   const float* __restrict__ gw,
                   const float* __restrict__ gb,
                   float* __restrict__ out)
{
    __shared__ __align__(16) char sm[SMEM_BYTES];
    float* lg  = (float*)sm;                 // logits, reuses B region
    float* gbs = (float*)(sm + 32768);       // bias
    const u32 sb = smem_u32(sm);

    const int tid  = threadIdx.x;
    const int wid  = tid >> 5;
    const int lane = tid & 31;
    const int m0   = blockIdx.x * MT;

    if (tid < NEXP) gbs[tid] = gb[tid];

    const ull NEG1 = packf2(-1.0f, -1.0f);

    // ---- per-thread A fragment source addresses (direct global -> register) ----
    const int ar = m0 + wid * 16 + (lane >> 2);
    const float* xp0 = x + (size_t)ar * HID + (lane & 3) * 2;
    const float* xp1 = xp0 + (size_t)8 * HID;

    // ---- B conversion mapping ----
    const int bn  = tid >> 2;
    const int bkt = tid & 3;
    const float* wp = gw + (size_t)bn * HID + bkt * 8;
    const int bst = (((bn >> 3) * 4 + bkt) * 8 + ((bn & 7) ^ bkt)) * 16;

    // ---- accumulators ----
    float ah[8][4], al[8][4], aM[8][4], aC[8][4];
#pragma unroll
    for (int i = 0; i < 8; i++)
#pragma unroll
        for (int j = 0; j < 4; j++) { ah[i][j] = 0.f; al[i][j] = 0.f; aM[i][j] = 0.f; aC[i][j] = 0.f; }

    // ---- prefetch chunk 0 ----
    float2 xc[2][2][2], xn[2][2][2];   // [row01][kstep][khalf]
    float4 wc[2], wn[2];
#pragma unroll
    for (int s = 0; s < 2; s++)
#pragma unroll
        for (int u = 0; u < 2; u++) {
            xc[0][s][u] = *(const float2*)(xp0 + s * 16 + u * 8);
            xc[1][s][u] = *(const float2*)(xp1 + s * 16 + u * 8);
        }
    wc[0] = *(const float4*)(wp);
    wc[1] = *(const float4*)(wp + 4);

    const int g = lane >> 3, r = lane & 7;   // ldmatrix lane-group / row

    // ---- chunk body (cur/nxt register sets passed by reference; 2-unrolled
    //      caller alternates them, eliminating rotation MOVs) ----
    auto body = [&](int c, float2 (&cx)[2][2][2], float4 (&cw)[2],
                    float2 (&nx)[2][2][2], float4 (&nw)[2]) {
        const int buf = c & 1;

        // convert + store B chunk (3 splits, STS.128 each)
        {
            u32 s0[4], s1[4], s2[4];
            split2f(cw[0].x, cw[0].y, NEG1, s0[0], s1[0], s2[0]);
            split2f(cw[0].z, cw[0].w, NEG1, s0[1], s1[1], s2[1]);
            split2f(cw[1].x, cw[1].y, NEG1, s0[2], s1[2], s2[2]);
            split2f(cw[1].z, cw[1].w, NEG1, s0[3], s1[3], s2[3]);
            char* p = sm + buf * BUFB + bst;
            *(uint4*)(p)              = make_uint4(s0[0], s0[1], s0[2], s0[3]);
            *(uint4*)(p + SPLITB)     = make_uint4(s1[0], s1[1], s1[2], s1[3]);
            *(uint4*)(p + 2 * SPLITB) = make_uint4(s2[0], s2[1], s2[2], s2[3]);
        }

        // issue next-chunk LDGs BEFORE the barrier (latency overlaps barrier+mma)
        const int cn = (c + 1 < NCH) ? (c + 1) * KC : 0;
#pragma unroll
        for (int s = 0; s < 2; s++)
#pragma unroll
            for (int u = 0; u < 2; u++) {
                nx[0][s][u] = *(const float2*)(xp0 + cn + s * 16 + u * 8);
                nx[1][s][u] = *(const float2*)(xp1 + cn + s * 16 + u * 8);
            }
        nw[0] = *(const float4*)(wp + cn);
        nw[1] = *(const float4*)(wp + cn + 4);

        __syncthreads();

        // ---- mma phase: product-pass-major to break accumulator RAW chains ----
        const u32 bb = sb + buf * BUFB;

#pragma unroll
        for (int s = 0; s < 2; s++) {
            // A splits for this k16-step
            u32 af0[4], af1[4], af2[4];
            split2f(cx[0][s][0].x, cx[0][s][0].y, NEG1, af0[0], af1[0], af2[0]);
            split2f(cx[1][s][0].x, cx[1][s][0].y, NEG1, af0[1], af1[1], af2[1]);
            split2f(cx[0][s][1].x, cx[0][s][1].y, NEG1, af0[2], af1[2], af2[2]);
            split2f(cx[1][s][1].x, cx[1][s][1].y, NEG1, af0[3], af1[3], af2[3]);

            const int kt = s * 2 + (g & 1);
            u32 ad[4];
#pragma unroll
            for (int tp = 0; tp < 4; tp++) {
                const int tn = tp * 2 + (g >> 1);
                ad[tp] = bb + (u32)(((tn * 4 + kt) * 8 + (r ^ kt)) * 16);
            }

            u32 b[4][4];
            // ---- split0 fragments: passes a0*b0 -> M, a1*b0 -> C, a2*b0 -> C ----
#pragma unroll
            for (int tp = 0; tp < 4; tp++)
                ldsm4(b[tp][0], b[tp][1], b[tp][2], b[tp][3], ad[tp]);
#pragma unroll
            for (int tp = 0; tp < 4; tp++)
#pragma unroll
                for (int t2 = 0; t2 < 2; t2++)
                    mma16816(aM[tp * 2 + t2], af0, b[tp][2 * t2], b[tp][2 * t2 + 1]);
#pragma unroll
            for (int tp = 0; tp < 4; tp++)
#pragma unroll
                for (int t2 = 0; t2 < 2; t2++)
                    mma16816(aC[tp * 2 + t2], af1, b[tp][2 * t2], b[tp][2 * t2 + 1]);
#pragma unroll
            for (int tp = 0; tp < 4; tp++)
#pragma unroll
                for (int t2 = 0; t2 < 2; t2++)
                    mma16816(aC[tp * 2 + t2], af2, b[tp][2 * t2], b[tp][2 * t2 + 1]);

            // ---- split1 fragments: passes a0*b1 -> C, a1*b1 -> C ----
#pragma unroll
            for (int tp = 0; tp < 4; tp++)
                ldsm4(b[tp][0], b[tp][1], b[tp][2], b[tp][3], ad[tp] + SPLITB);
#pragma unroll
            for (int tp = 0; tp < 4; tp++)
#pragma unroll
                for (int t2 = 0; t2 < 2; t2++)
                    mma16816(aC[tp * 2 + t2], af0, b[tp][2 * t2], b[tp][2 * t2 + 1]);
#pragma unroll
            for (int tp = 0; tp < 4; tp++)
#pragma unroll
                for (int t2 = 0; t2 < 2; t2++)
                    mma16816(aC[tp * 2 + t2], af1, b[tp][2 * t2], b[tp][2 * t2 + 1]);

            // ---- split2 fragments: pass a0*b2 -> C ----
#pragma unroll
            for (int tp = 0; tp < 4; tp++)
                ldsm4(b[tp][0], b[tp][1], b[tp][2], b[tp][3], ad[tp] + 2 * SPLITB);
#pragma unroll
            for (int tp = 0; tp < 4; tp++)
#pragma unroll
                for (int t2 = 0; t2 < 2; t2++)
                    mma16816(aC[tp * 2 + t2], af0, b[tp][2 * t2], b[tp][2 * t2 + 1]);
        }

        // ---- Fast2Sum flush of main accumulator every 2 chunks (K=64) ----
        if (c & 1) {
#pragma unroll
            for (int i = 0; i < 8; i++)
#pragma unroll
                for (int j = 0; j < 4; j++) {
                    dfadd(ah[i][j], al[i][j], aM[i][j]);
                    aM[i][j] = 0.f;
                }
        }
    };

#pragma unroll 1
    for (int c = 0; c < NCH; c += 2) {
        body(c,     xc, wc, xn, wn);
        body(c + 1, xn, wn, xc, wc);
    }

    __syncthreads();   // all mma reads of B region done before logits overwrite

    // ---- logits = ah + (al + corrections) + bias -> smem ----
    {
        const int row0 = wid * 16 + (lane >> 2);
#pragma unroll
        for (int t = 0; t < 8; t++)
#pragma unroll
            for (int k = 0; k < 4; k++) {
                int row = row0 + ((k >> 1) ? 8 : 0);
                int col = t * 8 + (lane & 3) * 2 + (k & 1);
                float v = fadd_rn(ah[t][k], fadd_rn(al[t][k], aC[t][k]));
                lg[row * NEXP + col] = fadd_rn(v, gbs[col]);
            }
    }
    __syncthreads();

    // ---- top-8 + softmax: one warp per token ----
    const unsigned FULL = 0xffffffffu;
    float* outw = out;
    float* outi = out + (size_t)TOKENS * TOPK;

    for (int t = wid; t < MT; t += 8) {
        float v0 = lg[t * NEXP + lane];
        float v1 = lg[t * NEXP + lane + 32];
        int   i0 = lane, i1 = lane + 32;

        float m = 0.f, ssum = 0.f, myv = 0.f;
        int myi = 0;

#pragma unroll
        for (int s = 0; s < TOPK; s++) {
            float v; int idx;
            if (v0 > v1 || (v0 == v1 && i0 < i1)) { v = v0; idx = i0; }
            else                                  { v = v1; idx = i1; }
#pragma unroll
            for (int off = 16; off > 0; off >>= 1) {
                float ov = __shfl_down_sync(FULL, v,   off);
                int   oi = __shfl_down_sync(FULL, idx, off);
                if (ov > v || (ov == v && oi < idx)) { v = ov; idx = oi; }
            }
            v   = __shfl_sync(FULL, v,   0);
            idx = __shfl_sync(FULL, idx, 0);

            if (s == 0) m = v;               // max (sorted descending)
            ssum += expf(v - m);
            if (lane == s) { myv = v; myi = idx; }

            if (idx == i0) v0 = -FLT_MAX;
            if (idx == i1) v1 = -FLT_MAX;
        }

        if (lane < TOPK) {
            int gidx = (m0 + t) * TOPK + lane;
            outw[gidx] = expf(myv - m) / ssum;
            outi[gidx] = (float)myi;
        }
    }
}

extern "C" void kernel_launch(void* const* d_in, const int* in_sizes, int n_in,
                              void* d_out, int out_size)
{
    const float* x  = (const float*)d_in[0];   // (16384, 4096) f32
    const float* gw = (const float*)d_in[1];   // (64, 4096)    f32
    const float* gb = (const float*)d_in[2];   // (64,)         f32
    float* out = (float*)d_out;                // [weights | indices] as f32

    gating_kernel<<<TOKENS / MT, NTHR>>>(x, gw, gb, out);
}

// round 13
// speedup vs baseline: 2.2628x; 1.3413x over previous
#include <cuda_runtime.h>
#include <cfloat>
#include <cmath>
#include <cstdint>

// ---- problem ----
#define TOKENS 16384
#define HID    4096
#define NEXP   64
#define TOPK   8

// ---- tiling ----
#define MT     128            // tokens per block
#define KC     32             // K per chunk
#define NCH    (HID / KC)     // 128 chunks
#define NTHR   256
#define SPLITB 4096           // one fp16 split of B chunk: 64n x 32k x 2B
#define BUFB   (2 * SPLITB)   // 8192 (2 splits)
// smem: [0, 32768) = B double-buffer (16384) reused as logits (32768); bias at 32768
#define SMEM_BYTES (32768 + 256)

typedef unsigned long long ull;
typedef uint32_t u32;

// ---- PTX helpers (plain-sm_103-safe) ----
__device__ __forceinline__ u32 smem_u32(const void* p) {
    u32 a;
    asm("{ .reg .u64 t; cvta.to.shared.u64 t, %1; cvt.u32.u64 %0, t; }"
        : "=r"(a) : "l"(p));
    return a;
}
__device__ __forceinline__ void ldsm4(u32& r0, u32& r1, u32& r2, u32& r3, u32 a) {
    asm volatile("ldmatrix.sync.aligned.m8n8.x4.shared.b16 {%0,%1,%2,%3}, [%4];"
                 : "=r"(r0), "=r"(r1), "=r"(r2), "=r"(r3) : "r"(a));
}
__device__ __forceinline__ void mma16816(float* c, const u32* a, u32 b0, u32 b1) {
    asm volatile(
        "mma.sync.aligned.m16n8k16.row.col.f32.f16.f16.f32 "
        "{%0,%1,%2,%3}, {%4,%5,%6,%7}, {%8,%9}, {%0,%1,%2,%3};"
        : "+f"(c[0]), "+f"(c[1]), "+f"(c[2]), "+f"(c[3])
        : "r"(a[0]), "r"(a[1]), "r"(a[2]), "r"(a[3]), "r"(b0), "r"(b1));
}

// ---- exact fp32 -> 2x fp16 split (packed, fast-math-immune) ----
__device__ __forceinline__ u32 cvth2(float lo, float hi) {
    u32 r;
    asm("cvt.rn.f16x2.f32 %0, %1, %2;" : "=r"(r) : "f"(hi), "f"(lo));
    return r;   // low half = lo (lower-k element), matches mma packing
}
__device__ __forceinline__ ull expandh(u32 p) {   // f16x2 -> f32x2 (exact)
    ull r;
    asm("{ .reg .b16 x, y; .reg .f32 fx, fy;\n\t"
        "mov.b32 {x, y}, %1;\n\t"
        "cvt.f32.f16 fx, x;\n\t"
        "cvt.f32.f16 fy, y;\n\t"
        "mov.b64 %0, {fx, fy}; }"
        : "=l"(r) : "r"(p));
    return r;
}
__device__ __forceinline__ ull packf2(float lo, float hi) {
    ull r;
    asm("mov.b64 %0, {%1, %2};" : "=l"(r) : "f"(lo), "f"(hi));
    return r;
}
__device__ __forceinline__ void unpackf2(ull v, float& lo, float& hi) {
    asm("mov.b64 {%0, %1}, %2;" : "=f"(lo), "=f"(hi) : "l"(v));
}
__device__ __forceinline__ ull fma2v(ull a, ull b, ull c) {
    ull r;
    asm("fma.rn.f32x2 %0, %1, %2, %3;" : "=l"(r) : "l"(a), "l"(b), "l"(c));
    return r;
}
__device__ __forceinline__ float fadd_rn(float a, float b) {
    float r; asm("add.rn.f32 %0, %1, %2;" : "=f"(r) : "f"(a), "f"(b)); return r;
}
__device__ __forceinline__ float fsub_rn(float a, float b) {
    float r; asm("sub.rn.f32 %0, %1, %2;" : "=f"(r) : "f"(a), "f"(b)); return r;
}
__device__ __forceinline__ void dfadd(float& h, float& l, float v) {
    float t = fadd_rn(h, v);
    float e = fadd_rn(fsub_rn(h, t), v);   // exact when |h| >= |v|
    l = fadd_rn(l, e);
    h = t;
}
// v -> q0 = f16x2(v), q1 = f16x2(v - f32(q0));  residual ~2^-22 |v| dropped
__device__ __forceinline__ void split1f(float vlo, float vhi, ull neg1,
                                        u32& q0, u32& q1) {
    ull v = packf2(vlo, vhi);
    q0 = cvth2(vlo, vhi);
    ull r1 = fma2v(expandh(q0), neg1, v);      // v - (f32)q0, exact
    float rl, rh; unpackf2(r1, rl, rh);
    q1 = cvth2(rl, rh);
}

__global__ __launch_bounds__(NTHR, 1)
void gating_kernel(const float* __restrict__ x,
                   const float* __restrict__ gw,
                   const float* __restrict__ gb,
                   float* __restrict__ out)
{
    __shared__ __align__(16) char sm[SMEM_BYTES];
    float* lg  = (float*)sm;                 // logits, reuses B region
    float* gbs = (float*)(sm + 32768);       // bias
    const u32 sb = smem_u32(sm);

    const int tid  = threadIdx.x;
    const int wid  = tid >> 5;
    const int lane = tid & 31;
    const int m0   = blockIdx.x * MT;

    if (tid < NEXP) gbs[tid] = gb[tid];

    const ull NEG1 = packf2(-1.0f, -1.0f);

    // ---- per-thread A fragment source addresses (direct global -> register) ----
    const int ar = m0 + wid * 16 + (lane >> 2);
    const float* xp0 = x + (size_t)ar * HID + (lane & 3) * 2;
    const float* xp1 = xp0 + (size_t)8 * HID;

    // ---- B conversion mapping ----
    const int bn  = tid >> 2;
    const int bkt = tid & 3;
    const float* wp = gw + (size_t)bn * HID + bkt * 8;
    const int bst = (((bn >> 3) * 4 + bkt) * 8 + ((bn & 7) ^ bkt)) * 16;

    // ---- accumulators ----
    float ah[8][4], al[8][4], aM[8][4], aC[8][4];
#pragma unroll
    for (int i = 0; i < 8; i++)
#pragma unroll
        for (int j = 0; j < 4; j++) { ah[i][j] = 0.f; al[i][j] = 0.f; aM[i][j] = 0.f; aC[i][j] = 0.f; }

    // ---- prefetch chunk 0 ----
    float2 xc[2][2][2], xn[2][2][2];   // [row01][kstep][khalf]
    float4 wc[2], wn[2];
#pragma unroll
    for (int s = 0; s < 2; s++)
#pragma unroll
        for (int u = 0; u < 2; u++) {
            xc[0][s][u] = *(const float2*)(xp0 + s * 16 + u * 8);
            xc[1][s][u] = *(const float2*)(xp1 + s * 16 + u * 8);
        }
    wc[0] = *(const float4*)(wp);
    wc[1] = *(const float4*)(wp + 4);

    const int g = lane >> 3, rr_ = lane & 7;   // ldmatrix lane-group / row

    // ---- chunk body (cur/nxt register sets alternate; no rotation MOVs) ----
    auto body = [&](int c, float2 (&cx)[2][2][2], float4 (&cw)[2],
                    float2 (&nx)[2][2][2], float4 (&nw)[2]) {
        const int buf = c & 1;

        // convert + store B chunk (2 splits, STS.128 each)
        {
            u32 s0[4], s1[4];
            split1f(cw[0].x, cw[0].y, NEG1, s0[0], s1[0]);
            split1f(cw[0].z, cw[0].w, NEG1, s0[1], s1[1]);
            split1f(cw[1].x, cw[1].y, NEG1, s0[2], s1[2]);
            split1f(cw[1].z, cw[1].w, NEG1, s0[3], s1[3]);
            char* p = sm + buf * BUFB + bst;
            *(uint4*)(p)          = make_uint4(s0[0], s0[1], s0[2], s0[3]);
            *(uint4*)(p + SPLITB) = make_uint4(s1[0], s1[1], s1[2], s1[3]);
        }

        // issue next-chunk LDGs BEFORE the barrier (latency overlaps barrier+mma)
        const int cn = (c + 1 < NCH) ? (c + 1) * KC : 0;
#pragma unroll
        for (int s = 0; s < 2; s++)
#pragma unroll
            for (int u = 0; u < 2; u++) {
                nx[0][s][u] = *(const float2*)(xp0 + cn + s * 16 + u * 8);
                nx[1][s][u] = *(const float2*)(xp1 + cn + s * 16 + u * 8);
            }
        nw[0] = *(const float4*)(wp + cn);
        nw[1] = *(const float4*)(wp + cn + 4);

        __syncthreads();

        // ---- mma phase: product-pass-major, 3 products ----
        const u32 bb = sb + buf * BUFB;

#pragma unroll
        for (int s = 0; s < 2; s++) {
            // A splits for this k16-step
            u32 af0[4], af1[4];
            split1f(cx[0][s][0].x, cx[0][s][0].y, NEG1, af0[0], af1[0]);
            split1f(cx[1][s][0].x, cx[1][s][0].y, NEG1, af0[1], af1[1]);
            split1f(cx[0][s][1].x, cx[0][s][1].y, NEG1, af0[2], af1[2]);
            split1f(cx[1][s][1].x, cx[1][s][1].y, NEG1, af0[3], af1[3]);

            const int kt = s * 2 + (g & 1);
            u32 ad[4];
#pragma unroll
            for (int tp = 0; tp < 4; tp++) {
                const int tn = tp * 2 + (g >> 1);
                ad[tp] = bb + (u32)(((tn * 4 + kt) * 8 + (rr_ ^ kt)) * 16);
            }

            u32 b[4][4];
            // ---- split0: a0*b0 -> M, a1*b0 -> C ----
#pragma unroll
            for (int tp = 0; tp < 4; tp++)
                ldsm4(b[tp][0], b[tp][1], b[tp][2], b[tp][3], ad[tp]);
#pragma unroll
            for (int tp = 0; tp < 4; tp++)
#pragma unroll
                for (int t2 = 0; t2 < 2; t2++)
                    mma16816(aM[tp * 2 + t2], af0, b[tp][2 * t2], b[tp][2 * t2 + 1]);
#pragma unroll
            for (int tp = 0; tp < 4; tp++)
#pragma unroll
                for (int t2 = 0; t2 < 2; t2++)
                    mma16816(aC[tp * 2 + t2], af1, b[tp][2 * t2], b[tp][2 * t2 + 1]);

            // ---- split1: a0*b1 -> C ----
#pragma unroll
            for (int tp = 0; tp < 4; tp++)
                ldsm4(b[tp][0], b[tp][1], b[tp][2], b[tp][3], ad[tp] + SPLITB);
#pragma unroll
            for (int tp = 0; tp < 4; tp++)
#pragma unroll
                for (int t2 = 0; t2 < 2; t2++)
                    mma16816(aC[tp * 2 + t2], af0, b[tp][2 * t2], b[tp][2 * t2 + 1]);
        }

        // ---- Fast2Sum flush of main accumulator every 2 chunks (K=64) ----
        if (c & 1) {
#pragma unroll
            for (int i = 0; i < 8; i++)
#pragma unroll
                for (int j = 0; j < 4; j++) {
                    dfadd(ah[i][j], al[i][j], aM[i][j]);
                    aM[i][j] = 0.f;
                }
        }
    };

#pragma unroll 1
    for (int c = 0; c < NCH; c += 2) {
        body(c,     xc, wc, xn, wn);
        body(c + 1, xn, wn, xc, wc);
    }

    __syncthreads();   // all mma reads of B region done before logits overwrite

    // ---- logits = ah + (al + corrections) + bias -> smem ----
    {
        const int row0 = wid * 16 + (lane >> 2);
#pragma unroll
        for (int t = 0; t < 8; t++)
#pragma unroll
            for (int k = 0; k < 4; k++) {
                int row = row0 + ((k >> 1) ? 8 : 0);
                int col = t * 8 + (lane & 3) * 2 + (k & 1);
                float v = fadd_rn(ah[t][k], fadd_rn(al[t][k], aC[t][k]));
                lg[row * NEXP + col] = fadd_rn(v, gbs[col]);
            }
    }
    __syncthreads();

    // ---- top-8 + softmax: one warp per token ----
    const unsigned FULL = 0xffffffffu;
    float* outw = out;
    float* outi = out + (size_t)TOKENS * TOPK;

    for (int t = wid; t < MT; t += 8) {
        float v0 = lg[t * NEXP + lane];
        float v1 = lg[t * NEXP + lane + 32];
        int   i0 = lane, i1 = lane + 32;

        float m = 0.f, ssum = 0.f, myv = 0.f;
        int myi = 0;

#pragma unroll
        for (int s = 0; s < TOPK; s++) {
            float v; int idx;
            if (v0 > v1 || (v0 == v1 && i0 < i1)) { v = v0; idx = i0; }
            else                                  { v = v1; idx = i1; }
#pragma unroll
            for (int off = 16; off > 0; off >>= 1) {
                float ov = __shfl_down_sync(FULL, v,   off);
                int   oi = __shfl_down_sync(FULL, idx, off);
                if (ov > v || (ov == v && oi < idx)) { v = ov; idx = oi; }
            }
            v   = __shfl_sync(FULL, v,   0);
            idx = __shfl_sync(FULL, idx, 0);

            if (s == 0) m = v;               // max (sorted descending)
            ssum += expf(v - m);
            if (lane == s) { myv = v; myi = idx; }

            if (idx == i0) v0 = -FLT_MAX;
            if (idx == i1) v1 = -FLT_MAX;
        }

        if (lane < TOPK) {
            int gidx = (m0 + t) * TOPK + lane;
            outw[gidx] = expf(myv - m) / ssum;
            outi[gidx] = (float)myi;
        }
    }
}

extern "C" void kernel_launch(void* const* d_in, const int* in_sizes, int n_in,
                              void* d_out, int out_size)
{
    const float* x  = (const float*)d_in[0];   // (16384, 4096) f32
    const float* gw = (const float*)d_in[1];   // (64, 4096)    f32
    const float* gb = (const float*)d_in[2];   // (64,)         f32
    float* out = (float*)d_out;                // [weights | indices] as f32

    gating_kernel<<<TOKENS / MT, NTHR>>>(x, gw, gb, out);
}